// round 6
// baseline (speedup 1.0000x reference)
#include <cuda_runtime.h>

#define BATCH   2097152
#define DIMC    32
#define INDIM   10
#define LAYERS  4
#define MB      17
#define EPSV    1e-5f

#define GRID_MAIN 2048
#define TPB       256
#define RPT       4                       // GRID_MAIN*TPB*RPT == BATCH exactly
#define STRIDE    (GRID_MAIN*TPB)

typedef unsigned long long u64;

// ---------------- scratch (__device__ globals: allocation-free) ----------------
__device__ __align__(16) float g_h[(size_t)DIMC * BATCH];   // planar [c][row]
__device__ __align__(16) float g_r[(size_t)DIMC * BATCH];   // planar [c][row]
__device__ __align__(16) float g_A[LAYERS * DIMC * DIMC];   // fused Fourier A+I, [l][in][out]
__device__ float g_partials[GRID_MAIN * 64];                // per-CTA [sum[32], sumsq[32]]
__device__ float g_scale[DIMC];                             // BN affine: y = x*scale + shift
__device__ float g_shift[DIMC];

// ---------------- packed f32x2 helpers ----------------
__device__ __forceinline__ u64 pk2(float a, float b){
    u64 r; asm("mov.b64 %0,{%1,%2};" : "=l"(r) : "f"(a), "f"(b)); return r;
}
__device__ __forceinline__ void up2(u64 v, float &a, float &b){
    asm("mov.b64 {%0,%1},%2;" : "=f"(a), "=f"(b) : "l"(v));
}
__device__ __forceinline__ u64 fma2(u64 a, u64 b, u64 c){
    u64 d; asm("fma.rn.f32x2 %0,%1,%2,%3;" : "=l"(d) : "l"(a), "l"(b), "l"(c)); return d;
}
__device__ __forceinline__ float siluf(float x){
    return x * __fdividef(1.0f, 1.0f + __expf(-x));
}

// 32->32 GEMV, packed pairs over outputs. w: u64 pair (out 2q,2q+1) at w[k*16+q].
__device__ __forceinline__ void gemm32(const float* s, const u64* w, u64* acc){
#pragma unroll
    for(int k = 0; k < DIMC; k++){
        u64 sp = pk2(s[k], s[k]);
        const ulonglong2* w2 = (const ulonglong2*)(w + k*16);
#pragma unroll
        for(int q = 0; q < 8; q++){
            ulonglong2 ww = w2[q];
            acc[2*q]   = fma2(sp, ww.x, acc[2*q]);
            acc[2*q+1] = fma2(sp, ww.y, acc[2*q+1]);
        }
    }
}

// ------- Fourier operator precompute: A' = A + I. One thread per element. -------
// irfft(rfft(e_j) @ W)[d]; c2r convention (imag of DC/Nyquist ignored).
__global__ void k_precompute_A(const float* __restrict__ wr, const float* __restrict__ wi){
    __shared__ double ct[32], st[32];
    int t = threadIdx.x;
    if(t < 32){
        double ang = 6.283185307179586476925286766559 * (double)t / 32.0;
        ct[t] = cos(ang); st[t] = sin(ang);
    }
    __syncthreads();
    int g = blockIdx.x * blockDim.x + t;               // 0..4095
    if(g >= LAYERS*DIMC*DIMC) return;
    int l = g >> 10, j = (g >> 5) & 31, d = g & 31;
    const float* WR = wr + l*MB*MB;
    const float* WI = wi + l*MB*MB;
    double v = 0.0;
    for(int k = 0; k < MB; k++){
        double re = 0.0, im = 0.0;
        for(int m = 0; m < MB; m++){
            double c = ct[(m*j)&31], s = st[(m*j)&31];   // rfft of e_j: c - i*s
            double a = (double)WR[m*MB + k], b = (double)WI[m*MB + k];
            re += c*a + s*b;
            im += c*b - s*a;
        }
        double al, be;
        if(k == 0)      { al = 1.0; be = 0.0; }
        else if(k == 16){ al = (d & 1) ? -1.0 : 1.0; be = 0.0; }
        else            { al = 2.0*ct[(k*d)&31]; be = 2.0*st[(k*d)&31]; }
        v += al*re - be*im;
    }
    v *= (1.0/32.0);
    if(j == d) v += 1.0;                                  // fold identity skip
    g_A[(l*DIMC + j)*DIMC + d] = (float)v;
}

// shared-tile stats: tile stride 35 floats/row -> conflict-free write & read
#define STATS_ACCUM() do{                                                      \
    __syncthreads();                                                           \
    _Pragma("unroll")                                                          \
    for(int j = 0; j < 32; j++){                                               \
        float v = tile[(mrow*32 + j)*35 + ch];                                 \
        ssum += v; ssq += v*v;                                                 \
    }                                                                          \
    __syncthreads();                                                           \
}while(0)

#define STATS_TAIL() do{                                                       \
    tile[mrow*64 + ch]      = ssum;                                            \
    tile[mrow*64 + 32 + ch] = ssq;                                             \
    __syncthreads();                                                           \
    if(threadIdx.x < 64){                                                      \
        float v = 0.f;                                                         \
        _Pragma("unroll")                                                      \
        for(int m = 0; m < 8; m++) v += tile[m*64 + threadIdx.x];              \
        g_partials[blockIdx.x*64 + threadIdx.x] = v;                           \
    }                                                                          \
}while(0)

// ---------------- stem: h = x@stem_w + b; stats(h) ----------------
__global__ __launch_bounds__(TPB) void k_stem(const float* __restrict__ x,
                                              const float* __restrict__ sw,
                                              const float* __restrict__ sb){
    __shared__ __align__(16) u64 wsh[INDIM*16];
    __shared__ u64 bsh[16];
    __shared__ float tile[8960];
    if(threadIdx.x < INDIM*16){
        int r = threadIdx.x >> 4, q = threadIdx.x & 15;
        wsh[threadIdx.x] = pk2(sw[r*DIMC + 2*q], sw[r*DIMC + 2*q + 1]);
    }
    if(threadIdx.x < 16) bsh[threadIdx.x] = pk2(sb[2*threadIdx.x], sb[2*threadIdx.x+1]);
    int ch = threadIdx.x & 31, mrow = threadIdx.x >> 5;
    float ssum = 0.f, ssq = 0.f;
    __syncthreads();
#pragma unroll 1
    for(int it = 0; it < RPT; ++it){
        int rowbase = blockIdx.x*TPB + it*STRIDE;
        int row = rowbase + threadIdx.x;
        // stage x coalesced
        for(int k = threadIdx.x; k < TPB*INDIM; k += TPB)
            tile[k] = x[(size_t)rowbase*INDIM + k];
        __syncthreads();
        float xv[INDIM];
#pragma unroll
        for(int i = 0; i < INDIM; i++) xv[i] = tile[threadIdx.x*INDIM + i];
        __syncthreads();
        u64 acc[16];
#pragma unroll
        for(int q = 0; q < 16; q++) acc[q] = bsh[q];
#pragma unroll
        for(int i = 0; i < INDIM; i++){
            u64 xp = pk2(xv[i], xv[i]);
            const ulonglong2* w2 = (const ulonglong2*)(wsh + i*16);
#pragma unroll
            for(int q = 0; q < 8; q++){
                ulonglong2 ww = w2[q];
                acc[2*q]   = fma2(xp, ww.x, acc[2*q]);
                acc[2*q+1] = fma2(xp, ww.y, acc[2*q+1]);
            }
        }
        float* trow = tile + threadIdx.x*35;
#pragma unroll
        for(int q = 0; q < 16; q++){
            float a, b; up2(acc[q], a, b);
            g_h[(size_t)(2*q)*BATCH + row]   = a;
            g_h[(size_t)(2*q+1)*BATCH + row] = b;
            trow[2*q] = a; trow[2*q+1] = b;
        }
        STATS_ACCUM();
    }
    STATS_TAIL();
}

// ---------------- finalize: partials -> BN scale/shift ----------------
__global__ void k_fin(const float* __restrict__ gamma, const float* __restrict__ beta, int layer){
    __shared__ float red[1024];
    __shared__ float tot[64];
    int t = threadIdx.x;                 // 1024 threads
    int col = t & 63, part = t >> 6;     // 16 groups x 128 rows
    const float* p = g_partials + (size_t)part*128*64 + col;
    float v = 0.f;
#pragma unroll 8
    for(int i = 0; i < 128; i++) v += p[(size_t)i*64];
    red[part*64 + col] = v;
    __syncthreads();
    if(t < 64){
        float s = 0.f;
#pragma unroll
        for(int q = 0; q < 16; q++) s += red[q*64 + t];
        tot[t] = s;
    }
    __syncthreads();
    if(t < DIMC){
        float mean = tot[t]      * (1.0f/(float)BATCH);
        float ex2  = tot[32 + t] * (1.0f/(float)BATCH);
        float var  = fmaxf(ex2 - mean*mean, 0.0f);
        float sc   = gamma[layer*DIMC + t] * rsqrtf(var + EPSV);
        g_scale[t] = sc;
        g_shift[t] = beta[layer*DIMC + t] - mean*sc;
    }
}

// ---------------- pass A: r = silu(bn1(h))@lin1 + b1; stats(r) ----------------
__global__ __launch_bounds__(TPB) void k_passA(const float* __restrict__ w1,
                                               const float* __restrict__ b1, int layer){
    __shared__ __align__(16) u64 wsh[512];
    __shared__ u64 bsh[16];
    __shared__ float2 bn[DIMC];
    __shared__ float tile[8960];
    {
        const u64* src = (const u64*)(w1 + layer*DIMC*DIMC);
        for(int i = threadIdx.x; i < 512; i += TPB) wsh[i] = src[i];
    }
    if(threadIdx.x < DIMC) bn[threadIdx.x] = make_float2(g_scale[threadIdx.x], g_shift[threadIdx.x]);
    if(threadIdx.x < 16){
        const float* bb = b1 + layer*DIMC;
        bsh[threadIdx.x] = pk2(bb[2*threadIdx.x], bb[2*threadIdx.x+1]);
    }
    int ch = threadIdx.x & 31, mrow = threadIdx.x >> 5;
    float ssum = 0.f, ssq = 0.f;
    int tid = blockIdx.x*TPB + threadIdx.x;
    __syncthreads();
#pragma unroll 1
    for(int it = 0; it < RPT; ++it){
        int row = tid + it*STRIDE;
        float s[DIMC];
#pragma unroll
        for(int c = 0; c < DIMC; c++) s[c] = g_h[(size_t)c*BATCH + row];
#pragma unroll
        for(int c = 0; c < DIMC; c++){
            float2 p = bn[c];
            s[c] = siluf(fmaf(s[c], p.x, p.y));
        }
        u64 acc[16];
#pragma unroll
        for(int q = 0; q < 16; q++) acc[q] = bsh[q];
        gemm32(s, wsh, acc);
        float* trow = tile + threadIdx.x*35;
#pragma unroll
        for(int q = 0; q < 16; q++){
            float a, b; up2(acc[q], a, b);
            g_r[(size_t)(2*q)*BATCH + row]   = a;
            g_r[(size_t)(2*q+1)*BATCH + row] = b;
            trow[2*q] = a; trow[2*q+1] = b;
        }
        STATS_ACCUM();
    }
    STATS_TAIL();
}

// ------- pass B: h' = silu( h@(A+I) + silu(bn2(r))@lin2 + b2 ); stats(h') -------
__global__ __launch_bounds__(TPB) void k_passB(const float* __restrict__ w2,
                                               const float* __restrict__ b2, int layer){
    __shared__ __align__(16) u64 wa[512];   // A+I
    __shared__ __align__(16) u64 wl[512];   // lin2
    __shared__ u64 bsh[16];
    __shared__ float2 bn[DIMC];
    __shared__ float tile[8960];
    {
        const u64* srcA = (const u64*)(g_A + layer*DIMC*DIMC);
        const u64* srcL = (const u64*)(w2  + layer*DIMC*DIMC);
        for(int i = threadIdx.x; i < 512; i += TPB){ wa[i] = srcA[i]; wl[i] = srcL[i]; }
    }
    if(threadIdx.x < DIMC) bn[threadIdx.x] = make_float2(g_scale[threadIdx.x], g_shift[threadIdx.x]);
    if(threadIdx.x < 16){
        const float* bb = b2 + layer*DIMC;
        bsh[threadIdx.x] = pk2(bb[2*threadIdx.x], bb[2*threadIdx.x+1]);
    }
    int ch = threadIdx.x & 31, mrow = threadIdx.x >> 5;
    float ssum = 0.f, ssq = 0.f;
    int tid = blockIdx.x*TPB + threadIdx.x;
    __syncthreads();
#pragma unroll 1
    for(int it = 0; it < RPT; ++it){
        int row = tid + it*STRIDE;
        float s[DIMC];
#pragma unroll
        for(int c = 0; c < DIMC; c++) s[c] = g_r[(size_t)c*BATCH + row];
#pragma unroll
        for(int c = 0; c < DIMC; c++){
            float2 p = bn[c];
            s[c] = siluf(fmaf(s[c], p.x, p.y));
        }
        u64 acc[16];
#pragma unroll
        for(int q = 0; q < 16; q++) acc[q] = bsh[q];
        gemm32(s, wl, acc);            // silu(bn2(r)) @ lin2 + b2
        // stream h through the A'-GEMM in chunks of 4 (caps registers, MLP=4)
#pragma unroll 4
        for(int k = 0; k < DIMC; k++){
            float hk = g_h[(size_t)k*BATCH + row];
            u64 hp = pk2(hk, hk);
            const ulonglong2* w2p = (const ulonglong2*)(wa + k*16);
#pragma unroll
            for(int q = 0; q < 8; q++){
                ulonglong2 ww = w2p[q];
                acc[2*q]   = fma2(hp, ww.x, acc[2*q]);
                acc[2*q+1] = fma2(hp, ww.y, acc[2*q+1]);
            }
        }
        float* trow = tile + threadIdx.x*35;
#pragma unroll
        for(int q = 0; q < 16; q++){
            float a, b; up2(acc[q], a, b);
            a = siluf(a); b = siluf(b);
            g_h[(size_t)(2*q)*BATCH + row]   = a;
            g_h[(size_t)(2*q+1)*BATCH + row] = b;
            trow[2*q] = a; trow[2*q+1] = b;
        }
        STATS_ACCUM();
    }
    STATS_TAIL();
}

// ---------------- head: out = h @ head_w + head_b (coalesced via smem) ----------------
__global__ __launch_bounds__(TPB) void k_head(const float* __restrict__ hw,
                                              const float* __restrict__ hb,
                                              float* __restrict__ out){
    __shared__ float wsh[DIMC*INDIM];
    __shared__ float bshf[INDIM];
    __shared__ float tile[TPB*INDIM];
    for(int i = threadIdx.x; i < DIMC*INDIM; i += TPB) wsh[i] = hw[i];
    if(threadIdx.x < INDIM) bshf[threadIdx.x] = hb[threadIdx.x];
    __syncthreads();
#pragma unroll 1
    for(int it = 0; it < RPT; ++it){
        int rowbase = blockIdx.x*TPB + it*STRIDE;
        int row = rowbase + threadIdx.x;
        float acc[INDIM];
#pragma unroll
        for(int i = 0; i < INDIM; i++) acc[i] = bshf[i];
#pragma unroll 4
        for(int c = 0; c < DIMC; c++){
            float h = g_h[(size_t)c*BATCH + row];
#pragma unroll
            for(int i = 0; i < INDIM; i++) acc[i] = fmaf(h, wsh[c*INDIM + i], acc[i]);
        }
        __syncthreads();
#pragma unroll
        for(int i = 0; i < INDIM; i++) tile[threadIdx.x*INDIM + i] = acc[i];
        __syncthreads();
        for(int k = threadIdx.x; k < TPB*INDIM; k += TPB)
            out[(size_t)rowbase*INDIM + k] = tile[k];
    }
}

// ---------------- launch ----------------
extern "C" void kernel_launch(void* const* d_in, const int* in_sizes, int n_in,
                              void* d_out, int out_size) {
    (void)in_sizes; (void)n_in; (void)out_size;
    const float* x      = (const float*)d_in[0];
    const float* stem_w = (const float*)d_in[1];
    const float* stem_b = (const float*)d_in[2];
    const float* fno_wr = (const float*)d_in[3];
    const float* fno_wi = (const float*)d_in[4];
    const float* bn1_g  = (const float*)d_in[5];
    const float* bn1_b  = (const float*)d_in[6];
    const float* lin1_w = (const float*)d_in[7];
    const float* lin1_b = (const float*)d_in[8];
    const float* bn2_g  = (const float*)d_in[9];
    const float* bn2_b  = (const float*)d_in[10];
    const float* lin2_w = (const float*)d_in[11];
    const float* lin2_b = (const float*)d_in[12];
    const float* head_w = (const float*)d_in[13];
    const float* head_b = (const float*)d_in[14];
    float* out = (float*)d_out;

    k_precompute_A<<<16, 256>>>(fno_wr, fno_wi);
    k_stem<<<GRID_MAIN, TPB>>>(x, stem_w, stem_b);
    for(int l = 0; l < LAYERS; l++){
        k_fin<<<1, 1024>>>(bn1_g, bn1_b, l);          // stats of h -> bn1 affine
        k_passA<<<GRID_MAIN, TPB>>>(lin1_w, lin1_b, l);
        k_fin<<<1, 1024>>>(bn2_g, bn2_b, l);          // stats of r -> bn2 affine
        k_passB<<<GRID_MAIN, TPB>>>(lin2_w, lin2_b, l);
    }
    k_head<<<GRID_MAIN, TPB>>>(head_w, head_b, out);
}